// round 4
// baseline (speedup 1.0000x reference)
#include <cuda_runtime.h>

// DWT1D bior3.5, J=3, fused single kernel.
// Per row (B*C = 1024 rows of N=16384):
//   level1: 16384 -> lo1(8197), hi1(8197)
//   level2: lo1   -> lo2(4104), hi2(4104)   (odd-pad == zero extension)
//   level3: lo2   -> lo3(2057), hi3(2057)
// Output layout (tuple order, concatenated): [x0(=lo3) | hi1 | hi2 | hi3]
//
// lo[n] = sum_l s[2n-10+l] * h0[l]  (cross-correlation, half=10 at every level)
// h1[i] = (i even ? -1 : +1) * h0[11-i]

#define N_IN   16384
#define O1     8197
#define O2     4104
#define O3     2057
#define NROWS  1024

// smem arrays padded so the vectorized fast path can read up to index 8t+7
// for the last group without bounds checks (pads are zero-filled).
#define SX_PAD   16400   // valid [0,16384), zeros [16384,16400)
#define SL1_PAD  8208    // valid [0,8197),  zeros [8197,8208)
#define SL2_PAD  4120    // valid [0,4104),  zeros [4104,4120)
#define SMEM_FLOATS (SX_PAD + SL1_PAD + SL2_PAD)   // 28728 -> 114912 bytes

#define OFF_X0  0
#define OFF_H1  ((size_t)NROWS * O3)                    // 2106368
#define OFF_H2  (OFF_H1 + (size_t)NROWS * O1)           // 10500096
#define OFF_H3  (OFF_H2 + (size_t)NROWS * O2)           // 14702592

// One analysis level. Each thread computes 4 consecutive output pairs
// (n0 = 4t .. 4t+3) from s[8t-12 .. 8t+7] loaded as 5x float4 (LDS.128).
// Left-edge groups (t<2, base<0) take the checked scalar path; at the left
// edge the max index is 2*7-10+11 = 15, always in range, so only idx>=0
// is checked there.
__device__ __forceinline__ void run_level(
    const float* __restrict__ s, int M,
    const float* __restrict__ h0, const float* __restrict__ h1,
    float* __restrict__ lo_smem,   // may be nullptr
    float* __restrict__ lo_gmem,   // may be nullptr
    float* __restrict__ hi_gmem)
{
    const int ngroups = (M + 3) >> 2;
    for (int t = threadIdx.x; t < ngroups; t += blockDim.x) {
        const int n0 = 4 * t;
        const int base = 8 * t - 12;
        float lo[4] = {0.f, 0.f, 0.f, 0.f};
        float hi[4] = {0.f, 0.f, 0.f, 0.f};

        if (base >= 0) {
            float v[20];
            #pragma unroll
            for (int q = 0; q < 5; q++) {
                float4 a = *(const float4*)(s + base + 4 * q);
                v[4 * q + 0] = a.x; v[4 * q + 1] = a.y;
                v[4 * q + 2] = a.z; v[4 * q + 3] = a.w;
            }
            #pragma unroll
            for (int j = 0; j < 4; j++) {
                #pragma unroll
                for (int l = 0; l < 12; l++) {
                    const float xv = v[2 + 2 * j + l];
                    lo[j] += xv * h0[l];
                    hi[j] += xv * h1[l];
                }
            }
        } else {
            #pragma unroll
            for (int j = 0; j < 4; j++) {
                const int n = n0 + j;
                #pragma unroll
                for (int l = 0; l < 12; l++) {
                    const int idx = 2 * n - 10 + l;
                    if (idx >= 0) {
                        const float xv = s[idx];
                        lo[j] += xv * h0[l];
                        hi[j] += xv * h1[l];
                    }
                }
            }
        }

        #pragma unroll
        for (int j = 0; j < 4; j++) {
            const int n = n0 + j;
            if (n < M) {
                if (lo_smem) lo_smem[n] = lo[j];
                if (lo_gmem) lo_gmem[n] = lo[j];
                hi_gmem[n] = hi[j];
            }
        }
    }
}

__global__ void __launch_bounds__(512, 1)
dwt1d_fused_kernel(const float* __restrict__ x,
                   const float* __restrict__ hac,
                   float* __restrict__ out)
{
    extern __shared__ float sm[];
    float* sx  = sm;
    float* sl1 = sm + SX_PAD;
    float* sl2 = sm + SX_PAD + SL1_PAD;

    const int row = blockIdx.x;
    const float* xr = x + (size_t)row * N_IN;

    // Filters -> registers (QMF pair derived from h0).
    float h0[12], h1[12];
    #pragma unroll
    for (int i = 0; i < 12; i++) h0[i] = __ldg(hac + i);
    #pragma unroll
    for (int i = 0; i < 12; i++)
        h1[i] = ((i & 1) ? 1.0f : -1.0f) * h0[11 - i];

    // Load input row into smem (float4, fully coalesced; row base 64KB-aligned).
    for (int i = threadIdx.x; i < N_IN / 4; i += blockDim.x)
        ((float4*)sx)[i] = ((const float4*)xr)[i];

    // Zero-fill the padding tails once; levels never overwrite them.
    {
        const int tid = threadIdx.x;
        if (tid < 16)                      sx [N_IN + tid]      = 0.f;   // [16384,16400)
        else if (tid >= 32 && tid < 43)    sl1[O1 + (tid - 32)] = 0.f;   // [8197,8208)
        else if (tid >= 64 && tid < 80)    sl2[O2 + (tid - 64)] = 0.f;   // [4104,4120)
    }
    __syncthreads();

    float* hi1 = out + OFF_H1 + (size_t)row * O1;
    float* hi2 = out + OFF_H2 + (size_t)row * O2;
    float* hi3 = out + OFF_H3 + (size_t)row * O3;
    float* x0  = out + OFF_X0 + (size_t)row * O3;

    run_level(sx,  O1, h0, h1, sl1,     nullptr, hi1);
    __syncthreads();
    run_level(sl1, O2, h0, h1, sl2,     nullptr, hi2);
    __syncthreads();
    run_level(sl2, O3, h0, h1, nullptr, x0,      hi3);
}

extern "C" void kernel_launch(void* const* d_in, const int* in_sizes, int n_in,
                              void* d_out, int out_size)
{
    // metadata order: x (16*64*16384), hac (12). Guard against swap.
    int xi = 0, hi = 1;
    if (n_in >= 2 && in_sizes[0] == 12) { xi = 1; hi = 0; }

    const float* x   = (const float*)d_in[xi];
    const float* hac = (const float*)d_in[hi];
    float* out = (float*)d_out;

    const size_t smem_bytes = (size_t)SMEM_FLOATS * sizeof(float);
    cudaFuncSetAttribute(dwt1d_fused_kernel,
                         cudaFuncAttributeMaxDynamicSharedMemorySize,
                         (int)smem_bytes);

    dwt1d_fused_kernel<<<NROWS, 512, smem_bytes>>>(x, hac, out);
}